// round 11
// baseline (speedup 1.0000x reference)
#include <cuda_runtime.h>
#include <math.h>

#define Bb 4
#define Ssz 2048
#define Dd 1024
#define Hh 16
#define DH 64
#define NBH (Bb*Hh)          // 64
#define BM2 64
#define BN2 64

// Scratch (allocation-free rule: device globals)
__device__ float g_Q[NBH * Ssz * DH];   // [bh][s][d]
__device__ float g_K[NBH * Ssz * DH];   // [bh][s][d]
__device__ float g_Kmean[NBH * DH];

// ---------------------------------------------------------------------------
// Kernel 1: fused QK projection  C = x @ W^T + b, de-interleaved into g_Q/g_K
// 128x128 tile, 8x8 microtile, software-pipelined global->smem staging.
// (round-9 version: measured best, 686us)
// ---------------------------------------------------------------------------
__global__ __launch_bounds__(256, 2) void proj_kernel(const float* __restrict__ x,
                                                      const float* __restrict__ W,
                                                      const float* __restrict__ bias) {
    __shared__ float As[8][128];   // [k][m]
    __shared__ float Bs[8][128];   // [k][n]
    const int m0 = blockIdx.y * 128;
    const int n0 = blockIdx.x * 128;
    const int t  = threadIdx.x;
    const int tx = t & 15, ty = t >> 4;
    const int lr = t >> 1, lk = (t & 1) * 4;

    float acc[8][8];
#pragma unroll
    for (int i = 0; i < 8; i++)
#pragma unroll
        for (int j = 0; j < 8; j++) acc[i][j] = 0.f;

    const float* Ap = x + (m0 + lr) * Dd + lk;
    const float* Bp = W + (n0 + lr) * Dd + lk;

    float4 av = *(const float4*)(Ap);
    float4 bv = *(const float4*)(Bp);

    for (int k0 = 0; k0 < Dd; k0 += 8) {
        __syncthreads();
        As[lk + 0][lr] = av.x; As[lk + 1][lr] = av.y;
        As[lk + 2][lr] = av.z; As[lk + 3][lr] = av.w;
        Bs[lk + 0][lr] = bv.x; Bs[lk + 1][lr] = bv.y;
        Bs[lk + 2][lr] = bv.z; Bs[lk + 3][lr] = bv.w;
        __syncthreads();
        int kn = (k0 + 8 < Dd) ? k0 + 8 : 0;
        av = *(const float4*)(Ap + kn);
        bv = *(const float4*)(Bp + kn);
#pragma unroll
        for (int k = 0; k < 8; k++) {
            float a[8], bb[8];
            float4 a0 = *(const float4*)&As[k][ty * 4];
            float4 a1 = *(const float4*)&As[k][64 + ty * 4];
            float4 b0 = *(const float4*)&Bs[k][tx * 4];
            float4 b1 = *(const float4*)&Bs[k][64 + tx * 4];
            a[0]=a0.x; a[1]=a0.y; a[2]=a0.z; a[3]=a0.w;
            a[4]=a1.x; a[5]=a1.y; a[6]=a1.z; a[7]=a1.w;
            bb[0]=b0.x; bb[1]=b0.y; bb[2]=b0.z; bb[3]=b0.w;
            bb[4]=b1.x; bb[5]=b1.y; bb[6]=b1.z; bb[7]=b1.w;
#pragma unroll
            for (int i = 0; i < 8; i++)
#pragma unroll
                for (int j = 0; j < 8; j++)
                    acc[i][j] = fmaf(a[i], bb[j], acc[i][j]);
        }
    }

    // Epilogue: route column n -> (q|k)[b][h][s][d]; n = (h*64+d)*2 + c
#pragma unroll
    for (int i = 0; i < 8; i++) {
        int rr = (i < 4) ? (ty * 4 + i) : (64 + ty * 4 + (i - 4));
        int m = m0 + rr;
        int b = m >> 11;
        int s = m & 2047;
#pragma unroll
        for (int j = 0; j < 8; j++) {
            int cc = (j < 4) ? (tx * 4 + j) : (64 + tx * 4 + (j - 4));
            int n = n0 + cc;
            float v = acc[i][j] + bias[n];
            int c  = n & 1;
            int hd = n >> 1;            // h*64 + d
            int h  = hd >> 6;
            int d  = hd & 63;
            int dst = ((b * Hh + h) * Ssz + s) * DH + d;
            if (c == 0) g_Q[dst] = v; else g_K[dst] = v;
        }
    }
}

// ---------------------------------------------------------------------------
// Kernel 2: k_mean[bh][d] = mean over s of g_K[bh][s][d]
// ---------------------------------------------------------------------------
__global__ __launch_bounds__(256) void kmean_kernel() {
    __shared__ float red[256];
    const int bh = blockIdx.x;
    const int t = threadIdx.x;
    const int d = t & 63, part = t >> 6;
    const float* kp = g_K + bh * (Ssz * DH) + d;
    float s = 0.f;
    for (int j = part; j < Ssz; j += 4) s += kp[j * DH];
    red[t] = s;
    __syncthreads();
    if (part == 0) {
        float tot = red[d] + red[64 + d] + red[128 + d] + red[192 + d];
        g_Kmean[bh * DH + d] = tot * (1.0f / Ssz);
    }
}

// selu(z) with fast exp (MUFU.EX2): error ~1e-7 rel, fine vs 1e-3 gate
__device__ __forceinline__ float selu_z(float z) {
    const float lam = 1.0507009873554805f;
    const float lam_al = 1.7580993408473766f;
    float e = __expf(z);
    return z > 0.f ? lam * z : fmaf(lam_al, e, -lam_al);
}

// ---------------------------------------------------------------------------
// Kernel 3: fused attention, BM=64 tiles for 3 CTAs/SM (6 warps/SMSP).
// Per block: one (b,h) and a 64-row i-tile. Loop j in 64-wide tiles:
//   S = Qs Ks^T ; f = selu(scale*S - mu_row) ; out += f @ V
// mu_row = scale * q_row . k_mean  (algebraic identity for the row mean)
// ---------------------------------------------------------------------------
__global__ __launch_bounds__(256, 3) void attn_kernel(const float* __restrict__ x,
                                                      float* __restrict__ out) {
    extern __shared__ float sm[];
    float* Qs = sm;                    // [64][64]    Qs[k*64 + r]
    float* Ks = Qs + 64 * 64;          // [64][68]    Ks[k*68 + c]
    float* Vs = Ks + 64 * 68;          // [64][64]    Vs[c*64 + d]
    float* Ssm = Vs + 64 * 64;         // [64][68]    Ssm[c*68 + r]
    float* mu = Ssm + 64 * 68;         // [64]
    float* km = mu + 64;               // [64]

    const int blk = blockIdx.x;
    const int bh = blk >> 5;           // 0..63
    const int it = blk & 31;           // 0..31
    const int b = bh >> 4, h = bh & 15;
    const int i0 = it * BM2;
    const int t = threadIdx.x;
    const int tx = t & 15, ty = t >> 4;

    // Load Q tile transposed: g_Q[bh][i0+r][k] -> Qs[k][r]
    {
        const float* qg = g_Q + (bh * Ssz + i0) * DH;
#pragma unroll
        for (int p = 0; p < 4; p++) {
            int idx = p * 256 + t;          // float4 index 0..1023
            int r = idx >> 4;               // 0..63
            int kq = (idx & 15) * 4;        // 0..60
            float4 v = *(const float4*)(qg + r * DH + kq);
            Qs[(kq + 0) * 64 + r] = v.x;
            Qs[(kq + 1) * 64 + r] = v.y;
            Qs[(kq + 2) * 64 + r] = v.z;
            Qs[(kq + 3) * 64 + r] = v.w;
        }
    }
    if (t < 64) km[t] = g_Kmean[bh * DH + t];
    __syncthreads();

    if (t < 64) {
        float s = 0.f;
#pragma unroll
        for (int k = 0; k < 64; k++) s = fmaf(Qs[k * 64 + t], km[k], s);
        mu[t] = s * 0.125f;                // scale = dh^-0.5 = 0.125
    }
    __syncthreads();

    float oacc[4][4];
#pragma unroll
    for (int i = 0; i < 4; i++)
#pragma unroll
        for (int j = 0; j < 4; j++) oacc[i][j] = 0.f;

    const float* xg = x + (b * Ssz) * Dd + h * DH;    // V[j][d] = xg[j*Dd + d]
    const float* kg = g_K + bh * (Ssz * DH);

    const float4 mu0 = *(const float4*)&mu[tx * 4];

    for (int j0 = 0; j0 < Ssz; j0 += BN2) {
        __syncthreads();   // WAR: previous iter's readers done
        // Load K (transposed) and V tiles: 64x64 each
#pragma unroll
        for (int p = 0; p < 4; p++) {
            int idx = p * 256 + t;
            int c = idx >> 4;
            int kq = (idx & 15) * 4;
            float4 kv = *(const float4*)(kg + (j0 + c) * DH + kq);
            Ks[(kq + 0) * 68 + c] = kv.x;
            Ks[(kq + 1) * 68 + c] = kv.y;
            Ks[(kq + 2) * 68 + c] = kv.z;
            Ks[(kq + 3) * 68 + c] = kv.w;
            float4 vv = *(const float4*)(xg + (j0 + c) * Dd + kq);
            *(float4*)&Vs[c * 64 + kq] = vv;
        }
        __syncthreads();

        // S-compute: thread owns rows tx*4+i, cols ty*4+j
        float sv[4][4];
#pragma unroll
        for (int i = 0; i < 4; i++)
#pragma unroll
            for (int j = 0; j < 4; j++) sv[i][j] = 0.f;
#pragma unroll
        for (int k = 0; k < 64; k++) {
            float4 q = *(const float4*)&Qs[k * 64 + tx * 4];
            float4 kk = *(const float4*)&Ks[k * 68 + ty * 4];
            float qa[4] = {q.x, q.y, q.z, q.w};
            float kb[4] = {kk.x, kk.y, kk.z, kk.w};
#pragma unroll
            for (int i = 0; i < 4; i++)
#pragma unroll
                for (int j = 0; j < 4; j++)
                    sv[i][j] = fmaf(qa[i], kb[j], sv[i][j]);
        }
        // selu(scale*s - mu); mu for rows tx*4..tx*4+3 is mu0
        float mua[4] = {mu0.x, mu0.y, mu0.z, mu0.w};
#pragma unroll
        for (int i = 0; i < 4; i++)
#pragma unroll
            for (int j = 0; j < 4; j++)
                sv[i][j] = selu_z(fmaf(sv[i][j], 0.125f, -mua[i]));
        // Write S tile: Ssm[c][r]
#pragma unroll
        for (int j = 0; j < 4; j++) {
            int c = ty * 4 + j;
            *(float4*)&Ssm[c * 68 + tx * 4] =
                make_float4(sv[0][j], sv[1][j], sv[2][j], sv[3][j]);
        }
        __syncthreads();

        // GEMM2: out[r][d] += S[r][c] * V[c][d]; rows ty*4+i, d tx*4+j
#pragma unroll
        for (int c = 0; c < 64; c++) {
            float4 s0 = *(const float4*)&Ssm[c * 68 + ty * 4];
            float4 vv = *(const float4*)&Vs[c * 64 + tx * 4];
            float sa[4] = {s0.x, s0.y, s0.z, s0.w};
            float vb[4] = {vv.x, vv.y, vv.z, vv.w};
#pragma unroll
            for (int i = 0; i < 4; i++)
#pragma unroll
                for (int j = 0; j < 4; j++)
                    oacc[i][j] = fmaf(sa[i], vb[j], oacc[i][j]);
        }
    }

    // Epilogue: out[b][i0+r][h*64 + d] = oacc * S^-0.5, rows ty*4+i
    const float os = 0.022097086912079608f;   // 1/sqrt(2048)
    float* og = out + (b * Ssz + i0) * Dd + h * DH;
#pragma unroll
    for (int i = 0; i < 4; i++) {
        int r = ty * 4 + i;
        float4 v = make_float4(oacc[i][0] * os, oacc[i][1] * os,
                               oacc[i][2] * os, oacc[i][3] * os);
        *(float4*)(og + r * Dd + tx * 4) = v;
    }
}

// ---------------------------------------------------------------------------
extern "C" void kernel_launch(void* const* d_in, const int* in_sizes, int n_in,
                              void* d_out, int out_size) {
    const float* x    = (const float*)d_in[0];
    const float* W    = (const float*)d_in[1];
    const float* bias = (const float*)d_in[2];
    float* out = (float*)d_out;

    const int ATTN_SMEM = (64 * 64 + 64 * 68 + 64 * 64 + 64 * 68 + 64 + 64) *
                          (int)sizeof(float);   // 68096 B
    cudaFuncSetAttribute(attn_kernel, cudaFuncAttributeMaxDynamicSharedMemorySize,
                         ATTN_SMEM);

    proj_kernel<<<dim3(16, 64), 256>>>(x, W, bias);
    kmean_kernel<<<NBH, 256>>>();
    attn_kernel<<<NBH * (Ssz / BM2), 256, ATTN_SMEM>>>(x, out);
}

// round 13
// speedup vs baseline: 1.1644x; 1.1644x over previous
#include <cuda_runtime.h>
#include <stdint.h>
#include <math.h>

#define Bb 4
#define Ssz 2048
#define Dd 1024
#define Hh 16
#define DH 64
#define NBH (Bb*Hh)          // 64
#define BM2 128
#define BN2 64

// Scratch (allocation-free rule: device globals)
__device__ float g_Q[NBH * Ssz * DH];   // [bh][s][d]
__device__ float g_K[NBH * Ssz * DH];   // [bh][s][d]
__device__ float g_Kmean[NBH * DH];

// ---------------------------------------------------------------------------
// mma.sync tf32 helpers (standard sm_80+ PTX; runs on HMMA pipe on sm_103)
// ---------------------------------------------------------------------------
__device__ __forceinline__ float tf32_hi(float a) {
    uint32_t u;
    asm("cvt.rna.tf32.f32 %0, %1;" : "=r"(u) : "f"(a));
    return __uint_as_float(u);
}

__device__ __forceinline__ void mma_tf32(float c[4], const float a[4],
                                         const float b0, const float b1) {
    asm volatile(
        "mma.sync.aligned.m16n8k8.row.col.f32.tf32.tf32.f32 "
        "{%0,%1,%2,%3}, {%4,%5,%6,%7}, {%8,%9}, {%0,%1,%2,%3};"
        : "+f"(c[0]), "+f"(c[1]), "+f"(c[2]), "+f"(c[3])
        : "r"(__float_as_uint(a[0])), "r"(__float_as_uint(a[1])),
          "r"(__float_as_uint(a[2])), "r"(__float_as_uint(a[3])),
          "r"(__float_as_uint(b0)), "r"(__float_as_uint(b1)));
}

// ---------------------------------------------------------------------------
// Kernel 1: QK projection via 3xTF32 mma.sync.  C = x @ W^T + b.
// 128x128 CTA tile, 8 warps in a 4x2 grid of 32x64 warp tiles.
// hi/lo split done once at staging into 4 smem tiles (pitch 136 ->
// conflict-free fragment loads: bank = 8k + n, all distinct).
// ---------------------------------------------------------------------------
#define PJP 136
__global__ __launch_bounds__(256, 2) void proj_kernel(const float* __restrict__ x,
                                                      const float* __restrict__ W,
                                                      const float* __restrict__ bias) {
    __shared__ float Ahi[8][PJP], Alo[8][PJP];
    __shared__ float Bhi[8][PJP], Blo[8][PJP];
    __shared__ float sbias[128];
    const int m0 = blockIdx.y * 128;
    const int n0 = blockIdx.x * 128;
    const int t  = threadIdx.x;
    const int w  = t >> 5, l = t & 31;
    const int wm = (w & 3) * 32;        // warp row offset (0,32,64,96)
    const int wn = (w >> 2) * 64;       // warp col offset (0,64)
    const int lr = t >> 1, lk = (t & 1) * 4;

    if (t < 128) sbias[t] = bias[n0 + t];

    float c[2][8][4];
#pragma unroll
    for (int i = 0; i < 2; i++)
#pragma unroll
        for (int j = 0; j < 8; j++)
#pragma unroll
            for (int q = 0; q < 4; q++) c[i][j][q] = 0.f;

    const float* Ap = x + (m0 + lr) * Dd + lk;
    const float* Bp = W + (n0 + lr) * Dd + lk;

    float4 av = *(const float4*)(Ap);
    float4 bv = *(const float4*)(Bp);

    const int ka = l & 3;               // fragment k (0..3)
    const int fr = l >> 2;              // fragment row/col (0..7)

    for (int k0 = 0; k0 < Dd; k0 += 8) {
        __syncthreads();
        {   // stage with hi/lo split
            float a4[4] = {av.x, av.y, av.z, av.w};
            float b4[4] = {bv.x, bv.y, bv.z, bv.w};
#pragma unroll
            for (int i = 0; i < 4; i++) {
                float ah = tf32_hi(a4[i]);
                Ahi[lk + i][lr] = ah;  Alo[lk + i][lr] = a4[i] - ah;
                float bh = tf32_hi(b4[i]);
                Bhi[lk + i][lr] = bh;  Blo[lk + i][lr] = b4[i] - bh;
            }
        }
        __syncthreads();
        int kn = (k0 + 8 < Dd) ? k0 + 8 : 0;
        av = *(const float4*)(Ap + kn);
        bv = *(const float4*)(Bp + kn);

        // A fragments for the two m16 subtiles
        float ah[2][4], al[2][4];
#pragma unroll
        for (int ms = 0; ms < 2; ms++) {
            int mb = wm + ms * 16 + fr;
            ah[ms][0] = Ahi[ka][mb];       ah[ms][1] = Ahi[ka][mb + 8];
            ah[ms][2] = Ahi[ka + 4][mb];   ah[ms][3] = Ahi[ka + 4][mb + 8];
            al[ms][0] = Alo[ka][mb];       al[ms][1] = Alo[ka][mb + 8];
            al[ms][2] = Alo[ka + 4][mb];   al[ms][3] = Alo[ka + 4][mb + 8];
        }
#pragma unroll
        for (int ns = 0; ns < 8; ns++) {
            int nb = wn + ns * 8 + fr;
            float bh0 = Bhi[ka][nb],     bh1 = Bhi[ka + 4][nb];
            float bl0 = Blo[ka][nb],     bl1 = Blo[ka + 4][nb];
#pragma unroll
            for (int ms = 0; ms < 2; ms++) {
                mma_tf32(c[ms][ns], ah[ms], bh0, bh1);   // hi*hi
                mma_tf32(c[ms][ns], ah[ms], bl0, bl1);   // hi*lo
                mma_tf32(c[ms][ns], al[ms], bh0, bh1);   // lo*hi
            }
        }
    }

    // Epilogue: c0:(r, nc) c1:(r, nc+1) c2:(r+8, nc) c3:(r+8, nc+1)
    // nc even -> q (c=0), odd -> k; d = nc>>1; h = blockIdx.x
    const int h = blockIdx.x;
#pragma unroll
    for (int ms = 0; ms < 2; ms++) {
#pragma unroll
        for (int half = 0; half < 2; half++) {
            int m = m0 + wm + ms * 16 + fr + half * 8;
            int b = m >> 11, s = m & 2047;
            float* qrow = g_Q + ((b * Hh + h) * Ssz + s) * DH;
            float* krow = g_K + ((b * Hh + h) * Ssz + s) * DH;
#pragma unroll
            for (int ns = 0; ns < 8; ns++) {
                int nc = wn + ns * 8 + 2 * ka;      // even
                float qv = c[ms][ns][2 * half + 0] + sbias[nc];
                float kv = c[ms][ns][2 * half + 1] + sbias[nc + 1];
                int d = nc >> 1;
                qrow[d] = qv;
                krow[d] = kv;
            }
        }
    }
}

// ---------------------------------------------------------------------------
// Kernel 2: k_mean[bh][d] = mean over s of g_K[bh][s][d]
// ---------------------------------------------------------------------------
__global__ __launch_bounds__(256) void kmean_kernel() {
    __shared__ float red[256];
    const int bh = blockIdx.x;
    const int t = threadIdx.x;
    const int d = t & 63, part = t >> 6;
    const float* kp = g_K + bh * (Ssz * DH) + d;
    float s = 0.f;
    for (int j = part; j < Ssz; j += 4) s += kp[j * DH];
    red[t] = s;
    __syncthreads();
    if (part == 0) {
        float tot = red[d] + red[64 + d] + red[128 + d] + red[192 + d];
        g_Kmean[bh * DH + d] = tot * (1.0f / Ssz);
    }
}

// selu(z) with fast exp (MUFU.EX2): error ~1e-7 rel, fine vs 1e-3 gate
__device__ __forceinline__ float selu_z(float z) {
    const float lam = 1.0507009873554805f;
    const float lam_al = 1.7580993408473766f;
    float e = __expf(z);
    return z > 0.f ? lam * z : fmaf(lam_al, e, -lam_al);
}

// ---------------------------------------------------------------------------
// Kernel 3: fused attention (round-9 build, measured best).
// ---------------------------------------------------------------------------
__global__ __launch_bounds__(256) void attn_kernel(const float* __restrict__ x,
                                                   float* __restrict__ out) {
    extern __shared__ float sm[];
    float* Qs = sm;                    // [64][128]   Qs[k*128 + r]
    float* Ks = Qs + 64 * 128;         // [64][68]    Ks[k*68 + c]
    float* Vs = Ks + 64 * 68;          // [64][64]    Vs[c*64 + d]
    float* Ssm = Vs + 64 * 64;         // [64][128]   Ssm[c*128 + r]
    float* mu = Ssm + 64 * 128;        // [128]
    float* km = mu + 128;              // [64]

    const int blk = blockIdx.x;
    const int bh = blk >> 4;           // 0..63
    const int it = blk & 15;
    const int b = bh >> 4, h = bh & 15;
    const int i0 = it * BM2;
    const int t = threadIdx.x;
    const int tx = t & 15, ty = t >> 4;

    {
        const float* qg = g_Q + (bh * Ssz + i0) * DH;
#pragma unroll
        for (int p = 0; p < 8; p++) {
            int idx = p * 256 + t;
            int r = idx >> 4;
            int kq = (idx & 15) * 4;
            float4 v = *(const float4*)(qg + r * DH + kq);
            Qs[(kq + 0) * 128 + r] = v.x;
            Qs[(kq + 1) * 128 + r] = v.y;
            Qs[(kq + 2) * 128 + r] = v.z;
            Qs[(kq + 3) * 128 + r] = v.w;
        }
    }
    if (t < 64) km[t] = g_Kmean[bh * DH + t];
    __syncthreads();

    if (t < 128) {
        float s = 0.f;
#pragma unroll
        for (int k = 0; k < 64; k++) s = fmaf(Qs[k * 128 + t], km[k], s);
        mu[t] = s * 0.125f;
    }
    __syncthreads();

    float oacc[8][4];
#pragma unroll
    for (int i = 0; i < 8; i++)
#pragma unroll
        for (int j = 0; j < 4; j++) oacc[i][j] = 0.f;

    const float* xg = x + (b * Ssz) * Dd + h * DH;
    const float* kg = g_K + bh * (Ssz * DH);

    float4 pk[4], pv[4];
#pragma unroll
    for (int p = 0; p < 4; p++) {
        int idx = p * 256 + t;
        int cc = idx >> 4;
        int kq = (idx & 15) * 4;
        pk[p] = *(const float4*)(kg + cc * DH + kq);
        pv[p] = *(const float4*)(xg + cc * Dd + kq);
    }

    for (int j0 = 0; j0 < Ssz; j0 += BN2) {
        __syncthreads();
#pragma unroll
        for (int p = 0; p < 4; p++) {
            int idx = p * 256 + t;
            int cc = idx >> 4;
            int kq = (idx & 15) * 4;
            Ks[(kq + 0) * 68 + cc] = pk[p].x;
            Ks[(kq + 1) * 68 + cc] = pk[p].y;
            Ks[(kq + 2) * 68 + cc] = pk[p].z;
            Ks[(kq + 3) * 68 + cc] = pk[p].w;
            *(float4*)&Vs[cc * 64 + kq] = pv[p];
        }
        __syncthreads();

        float sv[8][4];
#pragma unroll
        for (int i = 0; i < 8; i++)
#pragma unroll
            for (int j = 0; j < 4; j++) sv[i][j] = 0.f;
#pragma unroll
        for (int k = 0; k < 64; k++) {
            float4 q0 = *(const float4*)&Qs[k * 128 + tx * 4];
            float4 q1 = *(const float4*)&Qs[k * 128 + 64 + tx * 4];
            float4 kk = *(const float4*)&Ks[k * 68 + ty * 4];
            float qa[8] = {q0.x, q0.y, q0.z, q0.w, q1.x, q1.y, q1.z, q1.w};
            float kb[4] = {kk.x, kk.y, kk.z, kk.w};
#pragma unroll
            for (int i = 0; i < 8; i++)
#pragma unroll
                for (int j = 0; j < 4; j++)
                    sv[i][j] = fmaf(qa[i], kb[j], sv[i][j]);
        }
#pragma unroll
        for (int i = 0; i < 8; i++) {
            int r = (i < 4) ? (tx * 4 + i) : (64 + tx * 4 + (i - 4));
            float m_ = mu[r];
#pragma unroll
            for (int j = 0; j < 4; j++) {
                float z = fmaf(sv[i][j], 0.125f, -m_);
                sv[i][j] = selu_z(z);
            }
        }
#pragma unroll
        for (int j = 0; j < 4; j++) {
            int cc = ty * 4 + j;
            *(float4*)&Ssm[cc * 128 + tx * 4] =
                make_float4(sv[0][j], sv[1][j], sv[2][j], sv[3][j]);
            *(float4*)&Ssm[cc * 128 + 64 + tx * 4] =
                make_float4(sv[4][j], sv[5][j], sv[6][j], sv[7][j]);
        }

        {
            int jn = (j0 + BN2 < Ssz) ? j0 + BN2 : 0;
            const float* kgn = kg + jn * DH;
            const float* xgn = xg + jn * Dd;
#pragma unroll
            for (int p = 0; p < 4; p++) {
                int idx = p * 256 + t;
                int cc = idx >> 4;
                int kq = (idx & 15) * 4;
                pk[p] = *(const float4*)(kgn + cc * DH + kq);
                pv[p] = *(const float4*)(xgn + cc * Dd + kq);
            }
        }
        __syncthreads();

#pragma unroll
        for (int cc = 0; cc < 64; cc++) {
            float4 s0 = *(const float4*)&Ssm[cc * 128 + ty * 4];
            float4 s1 = *(const float4*)&Ssm[cc * 128 + 64 + ty * 4];
            float4 vv = *(const float4*)&Vs[cc * 64 + tx * 4];
            float sa[8] = {s0.x, s0.y, s0.z, s0.w, s1.x, s1.y, s1.z, s1.w};
            float vb[4] = {vv.x, vv.y, vv.z, vv.w};
#pragma unroll
            for (int i = 0; i < 8; i++)
#pragma unroll
                for (int j = 0; j < 4; j++)
                    oacc[i][j] = fmaf(sa[i], vb[j], oacc[i][j]);
        }
    }

    const float os = 0.022097086912079608f;   // 1/sqrt(2048)
    float* og = out + (b * Ssz + i0) * Dd + h * DH;
#pragma unroll
    for (int i = 0; i < 8; i++) {
        int r = (i < 4) ? (ty * 4 + i) : (64 + ty * 4 + (i - 4));
        float4 v = make_float4(oacc[i][0] * os, oacc[i][1] * os,
                               oacc[i][2] * os, oacc[i][3] * os);
        *(float4*)(og + r * Dd + tx * 4) = v;
    }
}

// ---------------------------------------------------------------------------
extern "C" void kernel_launch(void* const* d_in, const int* in_sizes, int n_in,
                              void* d_out, int out_size) {
    const float* x    = (const float*)d_in[0];
    const float* W    = (const float*)d_in[1];
    const float* bias = (const float*)d_in[2];
    float* out = (float*)d_out;

    const int ATTN_SMEM = (64 * 128 + 64 * 68 + 64 * 64 + 64 * 128 + 128 + 64) *
                          (int)sizeof(float);   // 100096 B
    cudaFuncSetAttribute(attn_kernel, cudaFuncAttributeMaxDynamicSharedMemorySize,
                         ATTN_SMEM);

    proj_kernel<<<dim3(16, 64), 256>>>(x, W, bias);
    kmean_kernel<<<NBH, 256>>>();
    attn_kernel<<<NBH * (Ssz / BM2), 256, ATTN_SMEM>>>(x, out);
}

// round 17
// speedup vs baseline: 1.4378x; 1.2348x over previous
#include <cuda_runtime.h>
#include <cuda_bf16.h>
#include <stdint.h>
#include <math.h>

#define Bb 4
#define Ssz 2048
#define Dd 1024
#define Hh 16
#define DH 64
#define NBH (Bb*Hh)          // 64
#define BM2 128
#define BN2 64

// Scratch (allocation-free rule: device globals)
__device__ float g_Q[NBH * Ssz * DH];   // [bh][s][d]
__device__ float g_K[NBH * Ssz * DH];   // [bh][s][d]
__device__ float g_Kmean[NBH * DH];

// ---------------------------------------------------------------------------
// mma.sync helpers (standard sm_80+ PTX; runs on HMMA pipe on sm_103)
// ---------------------------------------------------------------------------
__device__ __forceinline__ float tf32_hi(float a) {
    uint32_t u;
    asm("cvt.rna.tf32.f32 %0, %1;" : "=r"(u) : "f"(a));
    return __uint_as_float(u);
}

__device__ __forceinline__ void mma_tf32(float c[4], const float a[4],
                                         const float b0, const float b1) {
    asm volatile(
        "mma.sync.aligned.m16n8k8.row.col.f32.tf32.tf32.f32 "
        "{%0,%1,%2,%3}, {%4,%5,%6,%7}, {%8,%9}, {%0,%1,%2,%3};"
        : "+f"(c[0]), "+f"(c[1]), "+f"(c[2]), "+f"(c[3])
        : "r"(__float_as_uint(a[0])), "r"(__float_as_uint(a[1])),
          "r"(__float_as_uint(a[2])), "r"(__float_as_uint(a[3])),
          "r"(__float_as_uint(b0)), "r"(__float_as_uint(b1)));
}

__device__ __forceinline__ void mma_bf16(float c[4], const uint32_t a[4],
                                         uint32_t b0, uint32_t b1) {
    asm volatile(
        "mma.sync.aligned.m16n8k16.row.col.f32.bf16.bf16.f32 "
        "{%0,%1,%2,%3}, {%4,%5,%6,%7}, {%8,%9}, {%0,%1,%2,%3};"
        : "+f"(c[0]), "+f"(c[1]), "+f"(c[2]), "+f"(c[3])
        : "r"(a[0]), "r"(a[1]), "r"(a[2]), "r"(a[3]), "r"(b0), "r"(b1));
}

// split two floats into packed bf16x2 hi and lo parts (lower half = first elem)
__device__ __forceinline__ void bf16split2(float a, float b,
                                           uint32_t& h, uint32_t& l) {
    __nv_bfloat16 ha = __float2bfloat16_rn(a), hb = __float2bfloat16_rn(b);
    float ra = a - __bfloat162float(ha);
    float rb = b - __bfloat162float(hb);
    __nv_bfloat162 hp, lp;
    hp.x = ha; hp.y = hb;
    lp.x = __float2bfloat16_rn(ra); lp.y = __float2bfloat16_rn(rb);
    h = *reinterpret_cast<uint32_t*>(&hp);
    l = *reinterpret_cast<uint32_t*>(&lp);
}

// ---------------------------------------------------------------------------
// Kernel 1: QK projection via 3xTF32 mma.sync (round-13 build, 564us).
// ---------------------------------------------------------------------------
#define PJP 136
__global__ __launch_bounds__(256, 2) void proj_kernel(const float* __restrict__ x,
                                                      const float* __restrict__ W,
                                                      const float* __restrict__ bias) {
    __shared__ float Ahi[8][PJP], Alo[8][PJP];
    __shared__ float Bhi[8][PJP], Blo[8][PJP];
    __shared__ float sbias[128];
    const int m0 = blockIdx.y * 128;
    const int n0 = blockIdx.x * 128;
    const int t  = threadIdx.x;
    const int w  = t >> 5, l = t & 31;
    const int wm = (w & 3) * 32;
    const int wn = (w >> 2) * 64;
    const int lr = t >> 1, lk = (t & 1) * 4;

    if (t < 128) sbias[t] = bias[n0 + t];

    float c[2][8][4];
#pragma unroll
    for (int i = 0; i < 2; i++)
#pragma unroll
        for (int j = 0; j < 8; j++)
#pragma unroll
            for (int q = 0; q < 4; q++) c[i][j][q] = 0.f;

    const float* Ap = x + (m0 + lr) * Dd + lk;
    const float* Bp = W + (n0 + lr) * Dd + lk;

    float4 av = *(const float4*)(Ap);
    float4 bv = *(const float4*)(Bp);

    const int ka = l & 3;
    const int fr = l >> 2;

    for (int k0 = 0; k0 < Dd; k0 += 8) {
        __syncthreads();
        {
            float a4[4] = {av.x, av.y, av.z, av.w};
            float b4[4] = {bv.x, bv.y, bv.z, bv.w};
#pragma unroll
            for (int i = 0; i < 4; i++) {
                float ah = tf32_hi(a4[i]);
                Ahi[lk + i][lr] = ah;  Alo[lk + i][lr] = a4[i] - ah;
                float bh = tf32_hi(b4[i]);
                Bhi[lk + i][lr] = bh;  Blo[lk + i][lr] = b4[i] - bh;
            }
        }
        __syncthreads();
        int kn = (k0 + 8 < Dd) ? k0 + 8 : 0;
        av = *(const float4*)(Ap + kn);
        bv = *(const float4*)(Bp + kn);

        float ah[2][4], al[2][4];
#pragma unroll
        for (int ms = 0; ms < 2; ms++) {
            int mb = wm + ms * 16 + fr;
            ah[ms][0] = Ahi[ka][mb];       ah[ms][1] = Ahi[ka][mb + 8];
            ah[ms][2] = Ahi[ka + 4][mb];   ah[ms][3] = Ahi[ka + 4][mb + 8];
            al[ms][0] = Alo[ka][mb];       al[ms][1] = Alo[ka][mb + 8];
            al[ms][2] = Alo[ka + 4][mb];   al[ms][3] = Alo[ka + 4][mb + 8];
        }
#pragma unroll
        for (int ns = 0; ns < 8; ns++) {
            int nb = wn + ns * 8 + fr;
            float bh0 = Bhi[ka][nb],     bh1 = Bhi[ka + 4][nb];
            float bl0 = Blo[ka][nb],     bl1 = Blo[ka + 4][nb];
#pragma unroll
            for (int ms = 0; ms < 2; ms++) {
                mma_tf32(c[ms][ns], ah[ms], bh0, bh1);
                mma_tf32(c[ms][ns], ah[ms], bl0, bl1);
                mma_tf32(c[ms][ns], al[ms], bh0, bh1);
            }
        }
    }

    const int h = blockIdx.x;
#pragma unroll
    for (int ms = 0; ms < 2; ms++) {
#pragma unroll
        for (int half = 0; half < 2; half++) {
            int m = m0 + wm + ms * 16 + fr + half * 8;
            int b = m >> 11, s = m & 2047;
            float* qrow = g_Q + ((b * Hh + h) * Ssz + s) * DH;
            float* krow = g_K + ((b * Hh + h) * Ssz + s) * DH;
#pragma unroll
            for (int ns = 0; ns < 8; ns++) {
                int nc = wn + ns * 8 + 2 * ka;
                float qv = c[ms][ns][2 * half + 0] + sbias[nc];
                float kv = c[ms][ns][2 * half + 1] + sbias[nc + 1];
                int d = nc >> 1;
                qrow[d] = qv;
                krow[d] = kv;
            }
        }
    }
}

// ---------------------------------------------------------------------------
// Kernel 2: k_mean[bh][d] = mean over s of g_K[bh][s][d]
// ---------------------------------------------------------------------------
__global__ __launch_bounds__(256) void kmean_kernel() {
    __shared__ float red[256];
    const int bh = blockIdx.x;
    const int t = threadIdx.x;
    const int d = t & 63, part = t >> 6;
    const float* kp = g_K + bh * (Ssz * DH) + d;
    float s = 0.f;
    for (int j = part; j < Ssz; j += 4) s += kp[j * DH];
    red[t] = s;
    __syncthreads();
    if (part == 0) {
        float tot = red[d] + red[64 + d] + red[128 + d] + red[192 + d];
        g_Kmean[bh * DH + d] = tot * (1.0f / Ssz);
    }
}

// selu(z) with fast exp (MUFU.EX2)
__device__ __forceinline__ float selu_z(float z) {
    const float lam = 1.0507009873554805f;
    const float lam_al = 1.7580993408473766f;
    float e = __expf(z);
    return z > 0.f ? lam * z : fmaf(lam_al, e, -lam_al);
}

// ---------------------------------------------------------------------------
// Kernel 3: fused attention.
// GEMM1 (S = Q K^T): bf16x3 mma.sync m16n8k16, Q split once per CTA.
// GEMM2 (out += selu(S') V): scalar fp32 (exact), 8x4 microtile.
// ---------------------------------------------------------------------------
#define QP 36     // Q/K smem pitch in u32 pairs (conflict-free fragments)
#define SP 132    // Ssm pitch in floats (conflict-free fragment stores)

__global__ __launch_bounds__(256, 2) void attn_kernel(const float* __restrict__ x,
                                                      float* __restrict__ out) {
    extern __shared__ float sm[];
    uint32_t* Qh = (uint32_t*)sm;              // [128][QP]
    uint32_t* Ql = Qh + 128 * QP;              // [128][QP]
    uint32_t* Kh = Ql + 128 * QP;              // [64][QP]
    uint32_t* Kl = Kh + 64 * QP;               // [64][QP]
    float* Vs  = (float*)(Kl + 64 * QP);       // [64][64]
    float* Ssm = Vs + 64 * 64;                 // [64][SP]  Ssm[c*SP + r]
    float* mu  = Ssm + 64 * SP;                // [128]
    float* km  = mu + 128;                     // [64]

    const int blk = blockIdx.x;
    const int bh = blk >> 4;           // 0..63
    const int it = blk & 15;
    const int b = bh >> 4, h = bh & 15;
    const int i0 = it * BM2;
    const int t = threadIdx.x;
    const int w = t >> 5, l = t & 31;
    const int tx = t & 15, ty = t >> 4;

    const float* qg = g_Q + (bh * Ssz + i0) * DH;
    const float* kg = g_K + bh * (Ssz * DH);
    const float* xg = x + (b * Ssz) * Dd + h * DH;

    // ---- stage Q tile as bf16 hi/lo (once) ----
#pragma unroll
    for (int p = 0; p < 16; p++) {
        int pi = p * 256 + t;              // pair index 0..4095
        int r = pi >> 5, dp = pi & 31;
        float2 v = *(const float2*)(qg + r * DH + 2 * dp);
        uint32_t hh, ll;
        bf16split2(v.x, v.y, hh, ll);
        Qh[r * QP + dp] = hh;
        Ql[r * QP + dp] = ll;
    }
    if (t < 64) km[t] = g_Kmean[bh * DH + t];
    __syncthreads();

    // ---- mu from global Q (exact fp32) ----
    if (t < 128) {
        const float* qr = qg + t * DH;
        float s = 0.f;
#pragma unroll
        for (int d = 0; d < 64; d++) s = fmaf(qr[d], km[d], s);
        mu[t] = s * 0.125f;
    }

    // ---- preload A fragments (Q reused across all j-tiles) ----
    const int r0 = w * 16 + (l >> 2), r1 = r0 + 8;
    uint32_t ahf[4][4], alf[4][4];
#pragma unroll
    for (int kc = 0; kc < 4; kc++) {
        int dp0 = kc * 8 + (l & 3), dp1 = dp0 + 4;
        ahf[kc][0] = Qh[r0 * QP + dp0]; ahf[kc][1] = Qh[r1 * QP + dp0];
        ahf[kc][2] = Qh[r0 * QP + dp1]; ahf[kc][3] = Qh[r1 * QP + dp1];
        alf[kc][0] = Ql[r0 * QP + dp0]; alf[kc][1] = Ql[r1 * QP + dp0];
        alf[kc][2] = Ql[r0 * QP + dp1]; alf[kc][3] = Ql[r1 * QP + dp1];
    }

    // V prefetch (round-9 pattern)
    float4 pv[4];
#pragma unroll
    for (int p = 0; p < 4; p++) {
        int idx = p * 256 + t;
        int c = idx >> 4;
        int kq = (idx & 15) * 4;
        pv[p] = *(const float4*)(xg + c * Dd + kq);
    }
    __syncthreads();
    const float mu0 = mu[r0], mu1 = mu[r1];

    float oacc[8][4];
#pragma unroll
    for (int i = 0; i < 8; i++)
#pragma unroll
        for (int j = 0; j < 4; j++) oacc[i][j] = 0.f;

    for (int j0 = 0; j0 < Ssz; j0 += BN2) {
        __syncthreads();   // prev readers of Kh/Kl/Vs/Ssm done
        // ---- stage K tile as bf16 hi/lo + store V ----
#pragma unroll
        for (int p = 0; p < 8; p++) {
            int pi = p * 256 + t;          // 0..2047 pairs (64 rows x 32)
            int j = pi >> 5, dp = pi & 31;
            float2 v = *(const float2*)(kg + (j0 + j) * DH + 2 * dp);
            uint32_t hh, ll;
            bf16split2(v.x, v.y, hh, ll);
            Kh[j * QP + dp] = hh;
            Kl[j * QP + dp] = ll;
        }
#pragma unroll
        for (int p = 0; p < 4; p++) {
            int idx = p * 256 + t;
            int c = idx >> 4;
            int kq = (idx & 15) * 4;
            *(float4*)&Vs[c * 64 + kq] = pv[p];
        }
        __syncthreads();

        // ---- GEMM1: S = Q K^T via bf16x3 mma; selu; write Ssm ----
#pragma unroll
        for (int nc = 0; nc < 8; nc++) {
            float c4[4] = {0.f, 0.f, 0.f, 0.f};
            int jrow = nc * 8 + (l >> 2);
#pragma unroll
            for (int kc = 0; kc < 4; kc++) {
                int bi = jrow * QP + kc * 8 + (l & 3);
                uint32_t bh0 = Kh[bi], bh1 = Kh[bi + 4];
                uint32_t bl0 = Kl[bi], bl1 = Kl[bi + 4];
                mma_bf16(c4, ahf[kc], bh0, bh1);   // hi*hi
                mma_bf16(c4, ahf[kc], bl0, bl1);   // hi*lo
                mma_bf16(c4, alf[kc], bh0, bh1);   // lo*hi
            }
            int col = nc * 8 + 2 * (l & 3);
            Ssm[col * SP + r0]       = selu_z(fmaf(c4[0], 0.125f, -mu0));
            Ssm[(col + 1) * SP + r0] = selu_z(fmaf(c4[1], 0.125f, -mu0));
            Ssm[col * SP + r1]       = selu_z(fmaf(c4[2], 0.125f, -mu1));
            Ssm[(col + 1) * SP + r1] = selu_z(fmaf(c4[3], 0.125f, -mu1));
        }

        // prefetch next V (overlaps sync + GEMM2)
        {
            int jn = (j0 + BN2 < Ssz) ? j0 + BN2 : 0;
            const float* xgn = xg + jn * Dd;
#pragma unroll
            for (int p = 0; p < 4; p++) {
                int idx = p * 256 + t;
                int c = idx >> 4;
                int kq = (idx & 15) * 4;
                pv[p] = *(const float4*)(xgn + c * Dd + kq);
            }
        }
        __syncthreads();

        // ---- GEMM2: out[r][d] += F[r][c] * V[c][d]  (scalar fp32) ----
#pragma unroll
        for (int c = 0; c < 64; c++) {
            float4 s0 = *(const float4*)&Ssm[c * SP + ty * 4];
            float4 s1 = *(const float4*)&Ssm[c * SP + 64 + ty * 4];
            float4 vv = *(const float4*)&Vs[c * 64 + tx * 4];
            float sa[8] = {s0.x, s0.y, s0.z, s0.w, s1.x, s1.y, s1.z, s1.w};
            float vb[4] = {vv.x, vv.y, vv.z, vv.w};
#pragma unroll
            for (int i = 0; i < 8; i++)
#pragma unroll
                for (int j = 0; j < 4; j++)
                    oacc[i][j] = fmaf(sa[i], vb[j], oacc[i][j]);
        }
    }

    // Epilogue: out[b][i0+r][h*64 + d] = oacc * S^-0.5
    const float os = 0.022097086912079608f;   // 1/sqrt(2048)
    float* og = out + (b * Ssz + i0) * Dd + h * DH;
#pragma unroll
    for (int i = 0; i < 8; i++) {
        int r = (i < 4) ? (ty * 4 + i) : (64 + ty * 4 + (i - 4));
        float4 v = make_float4(oacc[i][0] * os, oacc[i][1] * os,
                               oacc[i][2] * os, oacc[i][3] * os);
        *(float4*)(og + r * Dd + tx * 4) = v;
    }
}

// ---------------------------------------------------------------------------
extern "C" void kernel_launch(void* const* d_in, const int* in_sizes, int n_in,
                              void* d_out, int out_size) {
    const float* x    = (const float*)d_in[0];
    const float* W    = (const float*)d_in[1];
    const float* bias = (const float*)d_in[2];
    float* out = (float*)d_out;

    const int ATTN_SMEM = (128 * QP * 2 + 64 * QP * 2) * 4 +
                          (64 * 64 + 64 * SP + 128 + 64) * 4;   // 106240 B
    cudaFuncSetAttribute(attn_kernel, cudaFuncAttributeMaxDynamicSharedMemorySize,
                         ATTN_SMEM);

    proj_kernel<<<dim3(16, 64), 256>>>(x, W, bias);
    kmean_kernel<<<NBH, 256>>>();
    attn_kernel<<<NBH * (Ssz / BM2), 256, ATTN_SMEM>>>(x, out);
}